// round 15
// baseline (speedup 1.0000x reference)
#include <cuda_runtime.h>

// out[b, s, d] = in[b, s, d] + PE[s, d]
// PE[s, 2i]   = sin(s / 10000^(2i/1024)),  PE[s, 2i+1] = cos(...)
//
// B=8, S=4096, D=1024, fp32 — 268 MB pure stream, DRAM-bound (~76%).
// R15 = R12/R14 geometry (2 batches/CTA x 256 thr, measured optimum) with
// WRITE-THROUGH stores (__stwt -> st.global.wt, SASS .WT coherence op).
// Rationale: LTS throughput (7.4 TB/s) > DRAM (6.0 TB/s) shows the input
// earns real cross-replay L2 hits; the never-read 134MB output stream
// competes for those lines. .WT removes output from L2 entirely — a real
// encoding change, unlike the inert createpolicy descriptor path (R3-R5).
// Fallback if this regresses: R14 (43.49us wall / 35.87us kernel).
//
// Measured design space (wall us): batches/CTA 8:45.1 | 4:44.3 |
// 2(256thr):43.5 | 2(128thr):45.2 | 1:45.8. Rejected: policy pinning,
// 256-bit v8 ops (-12%), persistent grid (-25%), accurate sincosf.

#define SEQ_LEN 4096
#define D_MODEL 1024
#define BATCH   8
#define BSPLIT  4                      // batch quarters per position
#define BPER    (BATCH / BSPLIT)       // 2 batches per CTA
#define THREADS 256                    // 256 x float4 = one PE row

__device__ __forceinline__ void fast_sincos(float ang, float* s, float* c) {
    // 2-term Cody-Waite: 2pi = HI + MID, HI exact in fp32.
    // k <= 652 here -> reduction error ~7e-8; __sincosf on [-pi,pi] ~4e-7.
    const float INV_2PI = 0.15915494309189535f;
    const float HI = 6.28125f;                 // exact
    const float MID = 1.9353071795864769e-3f;  // 2pi - HI
    float k = rintf(ang * INV_2PI);
    float r = fmaf(k, -HI, ang);
    r = fmaf(k, -MID, r);
    __sincosf(r, s, c);
}

__global__ void __launch_bounds__(THREADS, 8)
pe_add_kernel(const float4* __restrict__ in, float4* __restrict__ out) {
    const int pos  = blockIdx.x;       // sequence position 0..4095
    const int bseg = blockIdx.y;       // batch segment 0..3
    const int t    = threadIdx.x;      // float4 index within row 0..255

    // 32-bit element offsets in float4 units.
    const int row_f4       = D_MODEL / 4;            // 256
    const int batch_stride = SEQ_LEN * row_f4;       // 1,048,576
    int idx = (bseg * BPER) * batch_stride + pos * row_f4 + t;

    // Kick the first load before the trig prologue.
    float4 cur = __ldcs(in + idx);

    // PE for this thread's float4 (dims 4t..4t+3), computed once, reused 2x.
    const float LOG2_10000 = 13.287712379549449f;
    const float fpos = (float)pos;

    float e0 = (float)(4 * t)     * (1.0f / 1024.0f);
    float e1 = (float)(4 * t + 2) * (1.0f / 1024.0f);
    float a0 = fpos / exp2f(e0 * LOG2_10000);
    float a1 = fpos / exp2f(e1 * LOG2_10000);

    float s0, c0, s1, c1;
    fast_sincos(a0, &s0, &c0);
    fast_sincos(a1, &s1, &c1);

    const float4 pe = make_float4(s0, c0, s1, c1);

    // 2-deep pipeline over this CTA's 2 batches; write-through stores.
#pragma unroll
    for (int b = 0; b < BPER; ++b) {
        int next_idx = idx + batch_stride;
        float4 nxt;
        if (b < BPER - 1) nxt = __ldcs(in + next_idx);
        float4 v = cur;
        v.x += pe.x;
        v.y += pe.y;
        v.z += pe.z;
        v.w += pe.w;
        __stwt(out + idx, v);
        cur = nxt;
        idx = next_idx;
    }
}

extern "C" void kernel_launch(void* const* d_in, const int* in_sizes, int n_in,
                              void* d_out, int out_size) {
    const float4* in  = (const float4*)d_in[0];
    float4*       out = (float4*)d_out;
    dim3 grid(SEQ_LEN, BSPLIT);
    pe_add_kernel<<<grid, THREADS>>>(in, out);
}

// round 16
// speedup vs baseline: 1.0307x; 1.0307x over previous
#include <cuda_runtime.h>

// out[b, s, d] = in[b, s, d] + PE[s, d]
// PE[s, 2i]   = sin(s / 10000^(2i/1024)),  PE[s, 2i+1] = cos(...)
//
// B=8, S=4096, D=1024, fp32 — 268 MB pure stream. FINAL (R12/R14 form,
// reproduced best: 43.49us wall / 35.87us kernel, DRAM 75.7% = 6.0 TB/s
// vs the 33.5us floor at 100% of 8 TB/s spec — mixed-R/W HBM roofline).
//
// Design: grid (4096 pos, 4 batch-segments), 256 threads x float4 = one
// PE row. Each thread computes its 2 sin/cos pairs ONCE (Cody-Waite 2-term
// reduction mod 2pi + __sincosf MUFU; k<=652 -> err ~5e-7, rel_err 1.9e-5)
// and streams 2 batch copies with a 2-deep load pipeline, __ldcs/__stcs,
// 32-bit indexing, first load issued before the trig prologue.
//
// Full measured design space (wall us):
//   batches/CTA: 8:45.1 | 4:44.3 | 2(256thr):43.5 best | 2(128thr):45.2 | 1:45.8
//   L2 evict-policy pinning (full/partial): inert (R3-R5)
//   .WT write-through stores: 45.1 (R15, regression)
//   256-bit v8.f32 LDG/STG: 47.1 (R6, -12%)
//   persistent single-wave grid: 53.3 (R7, -25%)
//   accurate sincosf: equal accuracy, higher cost (R10 vs R12)

#define SEQ_LEN 4096
#define D_MODEL 1024
#define BATCH   8
#define BSPLIT  4                      // batch quarters per position
#define BPER    (BATCH / BSPLIT)       // 2 batches per CTA
#define THREADS 256                    // 256 x float4 = one PE row

__device__ __forceinline__ void fast_sincos(float ang, float* s, float* c) {
    // 2-term Cody-Waite: 2pi = HI + MID, HI exact in fp32.
    // k <= 652 here -> reduction error ~7e-8; __sincosf on [-pi,pi] ~4e-7.
    const float INV_2PI = 0.15915494309189535f;
    const float HI = 6.28125f;                 // exact
    const float MID = 1.9353071795864769e-3f;  // 2pi - HI
    float k = rintf(ang * INV_2PI);
    float r = fmaf(k, -HI, ang);
    r = fmaf(k, -MID, r);
    __sincosf(r, s, c);
}

__global__ void __launch_bounds__(THREADS, 8)
pe_add_kernel(const float4* __restrict__ in, float4* __restrict__ out) {
    const int pos  = blockIdx.x;       // sequence position 0..4095
    const int bseg = blockIdx.y;       // batch segment 0..3
    const int t    = threadIdx.x;      // float4 index within row 0..255

    // 32-bit element offsets in float4 units.
    const int row_f4       = D_MODEL / 4;            // 256
    const int batch_stride = SEQ_LEN * row_f4;       // 1,048,576
    int idx = (bseg * BPER) * batch_stride + pos * row_f4 + t;

    // Kick the first load before the trig prologue.
    float4 cur = __ldcs(in + idx);

    // PE for this thread's float4 (dims 4t..4t+3), computed once, reused 2x.
    const float LOG2_10000 = 13.287712379549449f;
    const float fpos = (float)pos;

    float e0 = (float)(4 * t)     * (1.0f / 1024.0f);
    float e1 = (float)(4 * t + 2) * (1.0f / 1024.0f);
    float a0 = fpos / exp2f(e0 * LOG2_10000);
    float a1 = fpos / exp2f(e1 * LOG2_10000);

    float s0, c0, s1, c1;
    fast_sincos(a0, &s0, &c0);
    fast_sincos(a1, &s1, &c1);

    const float4 pe = make_float4(s0, c0, s1, c1);

    // 2-deep pipeline over this CTA's 2 batches.
#pragma unroll
    for (int b = 0; b < BPER; ++b) {
        int next_idx = idx + batch_stride;
        float4 nxt;
        if (b < BPER - 1) nxt = __ldcs(in + next_idx);
        float4 v = cur;
        v.x += pe.x;
        v.y += pe.y;
        v.z += pe.z;
        v.w += pe.w;
        __stcs(out + idx, v);
        cur = nxt;
        idx = next_idx;
    }
}

extern "C" void kernel_launch(void* const* d_in, const int* in_sizes, int n_in,
                              void* d_out, int out_size) {
    const float4* in  = (const float4*)d_in[0];
    float4*       out = (float4*)d_out;
    dim3 grid(SEQ_LEN, BSPLIT);
    pe_add_kernel<<<grid, THREADS>>>(in, out);
}

// round 17
// speedup vs baseline: 1.0315x; 1.0007x over previous
#include <cuda_runtime.h>

// out[b, s, d] = in[b, s, d] + PE[s, d]
// PE[s, 2i]   = sin(s / 10000^(2i/1024)),  PE[s, 2i+1] = cos(...)
//
// B=8, S=4096, D=1024, fp32 — 268 MB pure stream. FINAL, CONVERGED.
// Best measured: 43.49us wall / 35.81us kernel, DRAM 75.9% (6.01 TB/s)
// vs the 33.5us floor at 100% of 8 TB/s spec — at the practical
// mixed-read/write HBM roofline for this chip.
//
// Design: grid (4096 pos, 4 batch-segments), 256 threads x float4 = one
// PE row. Each thread computes its 2 sin/cos pairs ONCE (Cody-Waite 2-term
// reduction mod 2pi + __sincosf MUFU; k<=652 -> abs err ~5e-7, rel_err
// 1.9e-5 = 50x margin) and streams 2 batch copies with a 2-deep load
// pipeline, __ldcs/__stcs, 32-bit indexing, first load issued before the
// trig prologue.
//
// Full measured design space (wall us):
//   batches/CTA: 8:45.1 | 4:44.3 | 2(256thr):43.5 BEST | 2(128thr):45.2 | 1:45.8
//   L2 evict-policy pinning (full/partial): inert (R3-R5)
//   .WT write-through stores: 45.1 (regression)
//   256-bit v8.f32 LDG/STG: 47.1 (-12%)
//   persistent single-wave grid: 53.3 (-25%)
//   accurate sincosf: equal accuracy, higher issue pressure

#define SEQ_LEN 4096
#define D_MODEL 1024
#define BATCH   8
#define BSPLIT  4                      // batch quarters per position
#define BPER    (BATCH / BSPLIT)       // 2 batches per CTA
#define THREADS 256                    // 256 x float4 = one PE row

__device__ __forceinline__ void fast_sincos(float ang, float* s, float* c) {
    // 2-term Cody-Waite: 2pi = HI + MID, HI exact in fp32.
    // k <= 652 here -> reduction error ~7e-8; __sincosf on [-pi,pi] ~4e-7.
    const float INV_2PI = 0.15915494309189535f;
    const float HI = 6.28125f;                 // exact
    const float MID = 1.9353071795864769e-3f;  // 2pi - HI
    float k = rintf(ang * INV_2PI);
    float r = fmaf(k, -HI, ang);
    r = fmaf(k, -MID, r);
    __sincosf(r, s, c);
}

__global__ void __launch_bounds__(THREADS, 8)
pe_add_kernel(const float4* __restrict__ in, float4* __restrict__ out) {
    const int pos  = blockIdx.x;       // sequence position 0..4095
    const int bseg = blockIdx.y;       // batch segment 0..3
    const int t    = threadIdx.x;      // float4 index within row 0..255

    // 32-bit element offsets in float4 units.
    const int row_f4       = D_MODEL / 4;            // 256
    const int batch_stride = SEQ_LEN * row_f4;       // 1,048,576
    int idx = (bseg * BPER) * batch_stride + pos * row_f4 + t;

    // Kick the first load before the trig prologue.
    float4 cur = __ldcs(in + idx);

    // PE for this thread's float4 (dims 4t..4t+3), computed once, reused 2x.
    const float LOG2_10000 = 13.287712379549449f;
    const float fpos = (float)pos;

    float e0 = (float)(4 * t)     * (1.0f / 1024.0f);
    float e1 = (float)(4 * t + 2) * (1.0f / 1024.0f);
    float a0 = fpos / exp2f(e0 * LOG2_10000);
    float a1 = fpos / exp2f(e1 * LOG2_10000);

    float s0, c0, s1, c1;
    fast_sincos(a0, &s0, &c0);
    fast_sincos(a1, &s1, &c1);

    const float4 pe = make_float4(s0, c0, s1, c1);

    // 2-deep pipeline over this CTA's 2 batches.
#pragma unroll
    for (int b = 0; b < BPER; ++b) {
        int next_idx = idx + batch_stride;
        float4 nxt;
        if (b < BPER - 1) nxt = __ldcs(in + next_idx);
        float4 v = cur;
        v.x += pe.x;
        v.y += pe.y;
        v.z += pe.z;
        v.w += pe.w;
        __stcs(out + idx, v);
        cur = nxt;
        idx = next_idx;
    }
}

extern "C" void kernel_launch(void* const* d_in, const int* in_sizes, int n_in,
                              void* d_out, int out_size) {
    const float4* in  = (const float4*)d_in[0];
    float4*       out = (float4*)d_out;
    dim3 grid(SEQ_LEN, BSPLIT);
    pe_add_kernel<<<grid, THREADS>>>(in, out);
}